// round 17
// baseline (speedup 1.0000x reference)
#include <cuda_runtime.h>
#include <math_constants.h>

// Problem constants (fixed by setup_inputs): B=8, N=128, H=256, F=1023
#define B_ 8
#define N_ 128
#define H_ 256

#define TM 16
#define TN 16
#define KSTR 20    // k-major row stride (floats) = 5*16B: float4-aligned;
                   // frag addr16 = 5k + ig -> <=2-way conflict within a warp

#define RSTRIDE 20 // reduction overlay stride (floats) = 80B: float4-aligned

#define NJT 8      // j-tiles per row

// Scratch: per-(row, j-tile) partial argmax (no counters, no atomics)
__device__ float g_pval[B_ * N_ * NJT];
__device__ int   g_pidx[B_ * N_ * NJT];

// ---------------------------------------------------------------------------
// Main kernel, 128 threads, 512 blocks (16x16 logits tile each; ~3.5
// blocks/SM resident -> cross-block latency hiding).
//   load: 32 rows (16 A=Xi, 16 B=Xj*W2) x 256 floats, 4 lanes/row; row-dots
//     r_i/s_j fused into loader regs (width-4 shuffle). Single barrier.
//   compute: 8 split-K groups of 16 threads, 4x4 microtile, k-range 32.
//   reduce: groups 1-7 -> smem overlay (stride 20, aligned); group 0 adds.
//   epilogue: + r_i + bias + s_j + W3[j+127-a(b,i)], mask, float4 store,
//     width-4 partial argmax -> scratch[NJT].
// ---------------------------------------------------------------------------
__global__ void __launch_bounds__(128)
pair_fused_kernel(const float* __restrict__ x,
                  const int* __restrict__ mask,
                  const float* __restrict__ W,
                  const float* __restrict__ bias,
                  float* __restrict__ out) {
    __shared__ __align__(16) float As[H_ * KSTR];   // 20 KB (k-major, 16 rows)
    __shared__ __align__(16) float Bs[H_ * KSTR];   // 20 KB (W2 folded)
    __shared__ float rs[32];               // [0:16) r_i, [16:32) s_j

    const int t  = threadIdx.x;
    const int jt = blockIdx.x, it = blockIdx.y, bb = blockIdx.z;
    const int i0 = it * TM, j0 = jt * TN;
    const float* xb = x + bb * N_ * H_;
    const float* W2 = W + 2 * H_;

    // ---- load + fold W2 + fused row-dots ----------------------------------
    {
        const int  row   = t >> 2;         // 0..31
        const int  lane4 = t & 3;          // 64-float segment
        const bool isA   = (row < 16);
        const int  lr    = isA ? row : row - 16;
        const int  grow  = (isA ? i0 : j0) + lr;
        const float* src  = xb + grow * H_ + lane4 * 64;
        const float* wsrc = (isA ? W : W + H_) + lane4 * 64;
        float rdot = 0.f;
        if (isA) {
#pragma unroll
            for (int q = 0; q < 16; q++) {
                float4 v  = ((const float4*)src)[q];
                float4 wv = ((const float4*)wsrc)[q];
                rdot += v.x * wv.x + v.y * wv.y + v.z * wv.z + v.w * wv.w;
                const int k = lane4 * 64 + q * 4;
                As[(k + 0) * KSTR + lr] = v.x;
                As[(k + 1) * KSTR + lr] = v.y;
                As[(k + 2) * KSTR + lr] = v.z;
                As[(k + 3) * KSTR + lr] = v.w;
            }
        } else {
            const float* w2s = W2 + lane4 * 64;
#pragma unroll
            for (int q = 0; q < 16; q++) {
                float4 v  = ((const float4*)src)[q];
                float4 wv = ((const float4*)wsrc)[q];
                float4 w2 = ((const float4*)w2s)[q];
                rdot += v.x * wv.x + v.y * wv.y + v.z * wv.z + v.w * wv.w;
                const int k = lane4 * 64 + q * 4;
                Bs[(k + 0) * KSTR + lr] = v.x * w2.x;
                Bs[(k + 1) * KSTR + lr] = v.y * w2.y;
                Bs[(k + 2) * KSTR + lr] = v.z * w2.z;
                Bs[(k + 3) * KSTR + lr] = v.w * w2.w;
            }
        }
        rdot += __shfl_down_sync(0xffffffffu, rdot, 1, 4);
        rdot += __shfl_down_sync(0xffffffffu, rdot, 2, 4);
        if (lane4 == 0) rs[(isA ? 0 : 16) + lr] = rdot;
    }
    __syncthreads();

    // ---- compute: 8 split-K groups of 16 threads, 4x4 microtile -----------
    const int g  = t >> 4;                 // 0..7: k slice [g*32, g*32+32)
    const int ts = t & 15;
    const int ig = ts >> 2;                // rows ig*4 .. ig*4+3
    const int jg = ts & 3;                 // cols jg*4 .. jg*4+3

    const float* ap = As + (g * 32) * KSTR + ig * 4;
    const float* bp = Bs + (g * 32) * KSTR + jg * 4;

    float4 acc0 = {0.f,0.f,0.f,0.f}, acc1 = {0.f,0.f,0.f,0.f};
    float4 acc2 = {0.f,0.f,0.f,0.f}, acc3 = {0.f,0.f,0.f,0.f};
#pragma unroll
    for (int kk = 0; kk < 32; kk++) {
        float4 af = *(const float4*)(ap + kk * KSTR);
        float4 bf = *(const float4*)(bp + kk * KSTR);
        acc0.x += af.x * bf.x; acc0.y += af.x * bf.y;
        acc0.z += af.x * bf.z; acc0.w += af.x * bf.w;
        acc1.x += af.y * bf.x; acc1.y += af.y * bf.y;
        acc1.z += af.y * bf.z; acc1.w += af.y * bf.w;
        acc2.x += af.z * bf.x; acc2.y += af.z * bf.y;
        acc2.z += af.z * bf.z; acc2.w += af.z * bf.w;
        acc3.x += af.w * bf.x; acc3.y += af.w * bf.y;
        acc3.z += af.w * bf.z; acc3.w += af.w * bf.w;
    }

    // ---- split-K reduction through As overlay (stride 20 = 80B aligned) ---
    __syncthreads();
    if (g != 0) {
        float* dst = As + ((g - 1) * 16 + ts) * RSTRIDE;
        *(float4*)(dst +  0) = acc0;  *(float4*)(dst +  4) = acc1;
        *(float4*)(dst +  8) = acc2;  *(float4*)(dst + 12) = acc3;
    }
    __syncthreads();

    // ---- epilogue (group 0: 16 threads, 16 outputs each) ------------------
    if (g == 0) {
#pragma unroll
        for (int q = 1; q < 8; q++) {
            const float* src = As + ((q - 1) * 16 + ts) * RSTRIDE;
            float4 p0 = *(const float4*)(src + 0);
            float4 p1 = *(const float4*)(src + 4);
            float4 p2 = *(const float4*)(src + 8);
            float4 p3 = *(const float4*)(src + 12);
            acc0.x += p0.x; acc0.y += p0.y; acc0.z += p0.z; acc0.w += p0.w;
            acc1.x += p1.x; acc1.y += p1.y; acc1.z += p1.z; acc1.w += p1.w;
            acc2.x += p2.x; acc2.y += p2.y; acc2.z += p2.z; acc2.w += p2.w;
            acc3.x += p3.x; acc3.y += p3.y; acc3.z += p3.z; acc3.w += p3.w;
        }

        const float  b0v = bias[0];
        const float* W3 = W + 3 * H_;
        const int* mb = mask + bb * N_;
        const int jb = j0 + jg * 4;
        const float4 sj = *(const float4*)(rs + 16 + jg * 4);
        const bool mj0 = mb[jb + 0] != 0, mj1 = mb[jb + 1] != 0;
        const bool mj2 = mb[jb + 2] != 0, mj3 = mb[jb + 3] != 0;

        float4 rowacc[4] = {acc0, acc1, acc2, acc3};
#pragma unroll
        for (int m = 0; m < 4; m++) {
            const int li = ig * 4 + m;
            const int i  = i0 + li;
            // repeat_interleave(dim=0).view quirk: one-hot row = (b*128+i)//8
            const int aidx = bb * 16 + (i >> 3);
            const float ri = rs[li] + b0v;
            const bool mi = mb[i] != 0;
            const float* w3r = W3 + 127 - aidx + jb;

            float v0 = rowacc[m].x + ri + sj.x + w3r[0];
            float v1 = rowacc[m].y + ri + sj.y + w3r[1];
            float v2 = rowacc[m].z + ri + sj.z + w3r[2];
            float v3 = rowacc[m].w + ri + sj.w + w3r[3];
            if (!(mi && mj0)) v0 = -CUDART_INF_F;
            if (!(mi && mj1)) v1 = -CUDART_INF_F;
            if (!(mi && mj2)) v2 = -CUDART_INF_F;
            if (!(mi && mj3)) v3 = -CUDART_INF_F;
            *(float4*)(out + (bb * N_ + i) * N_ + jb)
                = make_float4(v0, v1, v2, v3);

            // partial argmax over tile's 16 cols (first-occurrence ties)
            float best = v0; int bj = jb;
            if (v1 > best) { best = v1; bj = jb + 1; }
            if (v2 > best) { best = v2; bj = jb + 2; }
            if (v3 > best) { best = v3; bj = jb + 3; }
#pragma unroll
            for (int off = 2; off; off >>= 1) {
                float ov = __shfl_down_sync(0xffffffffu, best, off, 4);
                int   oj = __shfl_down_sync(0xffffffffu, bj,   off, 4);
                if (ov > best || (ov == best && oj < bj)) { best = ov; bj = oj; }
            }
            if (jg == 0) {
                g_pval[(bb * N_ + i) * NJT + jt] = best;
                g_pidx[(bb * N_ + i) * NJT + jt] = bj;
            }
        }
    }
}

// ---------------------------------------------------------------------------
// Decode kernel: combine the NJT=8 j-tile partials per row into preds.
// 8 blocks x 128 threads, one thread per row. First-occurrence tie-break:
// partials are scanned in ascending j-tile order and their indices ascend.
// ---------------------------------------------------------------------------
__global__ void __launch_bounds__(128)
argmax_decode_kernel(float* __restrict__ preds) {
    const int r = blockIdx.x * 128 + threadIdx.x;   // 0..1023
    if (r >= B_ * N_) return;
    float bv = g_pval[r * NJT + 0];
    int   bj = g_pidx[r * NJT + 0];
#pragma unroll
    for (int q = 1; q < NJT; q++) {
        float v = g_pval[r * NJT + q];
        if (v > bv) { bv = v; bj = g_pidx[r * NJT + q]; }   // idx grows with q
    }
    preds[r] = (float)bj;
}

// ---------------------------------------------------------------------------
extern "C" void kernel_launch(void* const* d_in, const int* in_sizes, int n_in,
                              void* d_out, int out_size) {
    const float* x    = (const float*)d_in[0];   // [8,128,256] float32
    const int*   mask = (const int*)d_in[1];     // [8,128] bool -> int32
    const float* W    = (const float*)d_in[2];   // [1,1023] float32
    const float* bias = (const float*)d_in[3];   // [1] float32
    float* out = (float*)d_out;

    const int nlog = B_ * N_ * N_;               // 131072
    float* preds = out + nlog;                   // [1024] as float

    dim3 grid(N_ / TN, N_ / TM, B_);             // (8,8,8) = 512 blocks
    pair_fused_kernel<<<grid, 128>>>(x, mask, W, bias, out);
    argmax_decode_kernel<<<8, 128>>>(preds);
}